// round 7
// baseline (speedup 1.0000x reference)
#include <cuda_runtime.h>
#include <math.h>

#define POOL 7
#define C 256
#define MAXROI 8192
#define NBUCKET 512
#define RPB 4            // ROIs per block in main kernel

typedef unsigned long long u64;

__device__ int g_counts[NBUCKET];
__device__ int g_offsets[NBUCKET];
__device__ int g_keys[MAXROI];
__device__ int g_order[MAXROI];

__device__ __forceinline__ u64 f32x2_mul(u64 a, u64 b) {
    u64 d; asm("mul.rn.f32x2 %0, %1, %2;" : "=l"(d) : "l"(a), "l"(b)); return d;
}
__device__ __forceinline__ u64 f32x2_fma(u64 a, u64 b, u64 c) {
    u64 d; asm("fma.rn.f32x2 %0, %1, %2, %3;" : "=l"(d) : "l"(a), "l"(b), "l"(c)); return d;
}
__device__ __forceinline__ u64 f32x2_pack(float v) {
    u64 d; asm("mov.b64 %0, {%1, %1};" : "=l"(d) : "f"(v)); return d;
}
__device__ __forceinline__ u64 bilerp2(u64 v00, u64 v01, u64 v10, u64 v11,
                                       u64 wtx2, u64 tx2, u64 wty2, u64 ty2) {
    u64 top = f32x2_fma(v01, tx2, f32x2_mul(v00, wtx2));
    u64 bot = f32x2_fma(v11, tx2, f32x2_mul(v10, wtx2));
    return f32x2_fma(bot, ty2, f32x2_mul(top, wty2));
}

__device__ __forceinline__ int roi_level(float h, float w, float img_area) {
    const float scale = sqrtf(fmaxf(h * w, 1e-12f)) * (sqrtf(img_area) / 224.0f);
    int lvl = 4 + (int)rintf(log2f(scale));   // round-half-even == jnp.round
    return min(max(lvl, 2), 5);
}

// ---------------- bucketing pipeline ----------------

__global__ void zero_counts_kernel() { g_counts[threadIdx.x] = 0; }

__global__ void count_kernel(const float* __restrict__ rois,
                             const int* __restrict__ image_shape, int BN, int N) {
    const int i = blockIdx.x * blockDim.x + threadIdx.x;
    if (i >= BN || i >= MAXROI) return;
    const float4 r = reinterpret_cast<const float4*>(rois)[i];
    const float img_area = (float)image_shape[0] * (float)image_shape[1];
    const int lvl = roi_level(r.z - r.x, r.w - r.y, img_area);
    const float cy = 0.5f * (r.x + r.z);
    const float cx = 0.5f * (r.y + r.w);
    const int tyi = min(7, max(0, (int)(cy * 8.0f)));
    const int txi = min(7, max(0, (int)(cx * 8.0f)));
    const int b = i / N;
    const int key = ((b * 4 + (lvl - 2)) * 8 + tyi) * 8 + txi;
    g_keys[i] = key;
    atomicAdd(&g_counts[key], 1);
}

__global__ void scan_kernel() {
    __shared__ int s[NBUCKET];
    const int t = threadIdx.x;
    const int c = g_counts[t];
    s[t] = c;
    __syncthreads();
    for (int d = 1; d < NBUCKET; d <<= 1) {
        int v = (t >= d) ? s[t - d] : 0;
        __syncthreads();
        s[t] += v;
        __syncthreads();
    }
    g_offsets[t] = s[t] - c;   // exclusive prefix
}

__global__ void scatter_kernel(int BN) {
    const int i = blockIdx.x * blockDim.x + threadIdx.x;
    if (i >= BN || i >= MAXROI) return;
    const int pos = atomicAdd(&g_offsets[g_keys[i]], 1);
    g_order[pos] = i;
}

// ---------------- main kernel ----------------
// Block (32,7): warp = pooled row, lane = channel quad (covers lane and lane+32).
// Each block processes RPB bucket-adjacent ROIs sequentially -> cross-ROI L1 reuse.
__global__ __launch_bounds__(224, 4)
void roi_align_kernel(const float* __restrict__ rois,
                      const int*   __restrict__ image_shape,
                      const float* __restrict__ p2,
                      const float* __restrict__ p3,
                      const float* __restrict__ p4,
                      const float* __restrict__ p5,
                      float* __restrict__ out,
                      int N, int BN)
{
    const int lane = threadIdx.x;
    const int py   = threadIdx.y;
    const float img_area = (float)image_shape[0] * (float)image_shape[1];
    const float gy = (float)py * (1.0f / (POOL - 1));

#pragma unroll 1
    for (int j = 0; j < RPB; ++j) {
        const int slot = blockIdx.x * RPB + j;
        if (slot >= BN) break;
        const int bn = g_order[slot];
        const int b  = bn / N;

        const float4 r = reinterpret_cast<const float4*>(rois)[bn];
        const float y1 = r.x, x1 = r.y, y2 = r.z, x2 = r.w;
        const float h = y2 - y1;
        const float w = x2 - x1;

        const int lvl = roi_level(h, w, img_area);
        const float* feat;
        int H;
        switch (lvl) {
            case 2:  feat = p2; H = 256; break;
            case 3:  feat = p3; H = 128; break;
            case 4:  feat = p4; H = 64;  break;
            default: feat = p5; H = 32;  break;
        }
        const float Hm1 = (float)(H - 1);
        const float Hm2 = (float)(H - 2);
        feat += (size_t)b * (size_t)H * (size_t)H * C;

        // y coordinate (warp-uniform)
        const float ysf = (y1 + gy * h) * Hm1;
        const float y0f = fminf(fmaxf(floorf(ysf), 0.0f), Hm2);
        const int   y0  = (int)y0f;
        const float ty  = fminf(fmaxf(ysf - y0f, 0.0f), 1.0f);
        const u64 wty2 = f32x2_pack(1.0f - ty);
        const u64 ty2  = f32x2_pack(ty);

        const ulonglong2* row0 = reinterpret_cast<const ulonglong2*>(feat) +
                                 (size_t)y0 * H * 64 + lane;
        const ulonglong2* row1 = row0 + (size_t)H * 64;

        int   xo[POOL];
        float txa[POOL];
#pragma unroll
        for (int px = 0; px < POOL; ++px) {
            const float gx  = (float)px * (1.0f / (POOL - 1));
            const float xsf = (x1 + gx * w) * Hm1;
            const float x0f = fminf(fmaxf(floorf(xsf), 0.0f), Hm2);
            xo[px]  = (int)x0f * 64;
            txa[px] = fminf(fmaxf(xsf - x0f, 0.0f), 1.0f);
        }

        float4* out_base = reinterpret_cast<float4*>(out + (size_t)bn * (POOL * POOL * C))
                           + (size_t)py * POOL * 64 + lane;

        // column-carry walk (x0 non-decreasing, block-uniform)
        ulonglong2 s00a, s00b, s01a, s01b, s10a, s10b, s11a, s11b;
        int cx = -128;

#pragma unroll
        for (int px = 0; px < POOL; ++px) {
            const int x = xo[px];
            if (x == cx + 64) {
                s00a = s01a; s00b = s01b;
                s10a = s11a; s10b = s11b;
                const ulonglong2* q0 = row0 + (x + 64);
                const ulonglong2* q1 = row1 + (x + 64);
                s01a = q0[0]; s01b = q0[32];
                s11a = q1[0]; s11b = q1[32];
            } else if (x != cx) {
                const ulonglong2* q0 = row0 + x;
                const ulonglong2* q1 = row1 + x;
                s00a = q0[0];  s00b = q0[32];
                s01a = q0[64]; s01b = q0[96];
                s10a = q1[0];  s10b = q1[32];
                s11a = q1[64]; s11b = q1[96];
            }
            cx = x;

            const float tx = txa[px];
            const u64 wtx2 = f32x2_pack(1.0f - tx);
            const u64 tx2  = f32x2_pack(tx);

            ulonglong2 ra, rb;
            ra.x = bilerp2(s00a.x, s01a.x, s10a.x, s11a.x, wtx2, tx2, wty2, ty2);
            ra.y = bilerp2(s00a.y, s01a.y, s10a.y, s11a.y, wtx2, tx2, wty2, ty2);
            rb.x = bilerp2(s00b.x, s01b.x, s10b.x, s11b.x, wtx2, tx2, wty2, ty2);
            rb.y = bilerp2(s00b.y, s01b.y, s10b.y, s11b.y, wtx2, tx2, wty2, ty2);

            __stcs(out_base + px * 64,      *reinterpret_cast<float4*>(&ra));
            __stcs(out_base + px * 64 + 32, *reinterpret_cast<float4*>(&rb));
        }
    }
}

extern "C" void kernel_launch(void* const* d_in, const int* in_sizes, int n_in,
                              void* d_out, int out_size)
{
    const float* rois        = (const float*)d_in[0];
    const int*   image_shape = (const int*)  d_in[1];
    const float* p2          = (const float*)d_in[2];
    const float* p3          = (const float*)d_in[3];
    const float* p4          = (const float*)d_in[4];
    const float* p5          = (const float*)d_in[5];
    float*       out         = (float*)d_out;

    const int B  = in_sizes[2] / (256 * 256 * 256);
    const int N  = in_sizes[0] / (4 * B);
    const int BN = B * N;

    // bucketing pipeline (all graph-capturable kernel launches)
    zero_counts_kernel<<<1, NBUCKET>>>();
    count_kernel<<<(BN + 255) / 256, 256>>>(rois, image_shape, BN, N);
    scan_kernel<<<1, NBUCKET>>>();
    scatter_kernel<<<(BN + 255) / 256, 256>>>(BN);

    dim3 block(32, 7);
    dim3 grid((BN + RPB - 1) / RPB);
    roi_align_kernel<<<grid, block>>>(rois, image_shape, p2, p3, p4, p5, out, N, BN);
}

// round 8
// speedup vs baseline: 1.0142x; 1.0142x over previous
#include <cuda_runtime.h>
#include <math.h>

#define POOL 7
#define C 256
#define MAXROI 8192
#define NB 512

typedef unsigned long long u64;

__device__ int g_order[MAXROI];

__device__ __forceinline__ u64 f32x2_mul(u64 a, u64 b) {
    u64 d; asm("mul.rn.f32x2 %0, %1, %2;" : "=l"(d) : "l"(a), "l"(b)); return d;
}
__device__ __forceinline__ u64 f32x2_fma(u64 a, u64 b, u64 c) {
    u64 d; asm("fma.rn.f32x2 %0, %1, %2, %3;" : "=l"(d) : "l"(a), "l"(b), "l"(c)); return d;
}
__device__ __forceinline__ u64 f32x2_pack(float v) {
    u64 d; asm("mov.b64 %0, {%1, %1};" : "=l"(d) : "f"(v)); return d;
}
__device__ __forceinline__ u64 bilerp2(u64 v00, u64 v01, u64 v10, u64 v11,
                                       u64 wtx2, u64 tx2, u64 wty2, u64 ty2) {
    u64 top = f32x2_fma(v01, tx2, f32x2_mul(v00, wtx2));
    u64 bot = f32x2_fma(v11, tx2, f32x2_mul(v10, wtx2));
    return f32x2_fma(bot, ty2, f32x2_mul(top, wty2));
}
__device__ __forceinline__ int roi_level(float h, float w, float img_area) {
    const float scale = sqrtf(fmaxf(h * w, 1e-12f)) * (sqrtf(img_area) / 224.0f);
    int lvl = 4 + (int)rintf(log2f(scale));   // round-half-even == jnp.round
    return min(max(lvl, 2), 5);
}

// ---------- single-block binning: count -> scan -> scatter, all in smem ----------
__global__ void bin_kernel(const float* __restrict__ rois,
                           const int* __restrict__ image_shape,
                           int BN, int N)
{
    __shared__ int cnt[NB];
    __shared__ int off[NB];
    const int t = threadIdx.x;
    cnt[t] = 0;
    __syncthreads();

    const float img_area = (float)image_shape[0] * (float)image_shape[1];
    int keys[(MAXROI + NB - 1) / NB];
    int m = 0;
    for (int i = t; i < BN; i += NB) {
        const float4 r = reinterpret_cast<const float4*>(rois)[i];
        const int lvl = roi_level(r.z - r.x, r.w - r.y, img_area);
        const float cy = 0.5f * (r.x + r.z);
        const float cx = 0.5f * (r.y + r.w);
        const int ty8 = min(7, max(0, (int)(cy * 8.0f)));
        const int tx8 = min(7, max(0, (int)(cx * 8.0f)));
        int key = (((i / N) * 4 + (lvl - 2)) * 8 + ty8) * 8 + tx8;
        key = min(key, NB - 1);
        keys[m++] = key;
        atomicAdd(&cnt[key], 1);
    }
    __syncthreads();

    const int c = cnt[t];
    for (int d = 1; d < NB; d <<= 1) {          // inclusive Hillis-Steele
        int v = (t >= d) ? cnt[t - d] : 0;
        __syncthreads();
        cnt[t] += v;
        __syncthreads();
    }
    off[t] = cnt[t] - c;                         // exclusive prefix
    __syncthreads();

    m = 0;
    for (int i = t; i < BN; i += NB) {
        const int pos = atomicAdd(&off[keys[m++]], 1);
        g_order[pos] = i;
    }
}

// ---------- main kernel ----------

struct Ctx {
    const ulonglong2* row0;
    const ulonglong2* row1;
    u64 wty2, ty2;
    int   xo[POOL];
    float txa[POOL];
    float4* outb;
};

__device__ __forceinline__ void setup_ctx(
    Ctx& c, int bn, int N, const float* __restrict__ rois, float img_area,
    const float* __restrict__ p2, const float* __restrict__ p3,
    const float* __restrict__ p4, const float* __restrict__ p5,
    float* __restrict__ out, int lane, float gy, int py)
{
    const int b = bn / N;
    const float4 r = reinterpret_cast<const float4*>(rois)[bn];
    const float y1 = r.x, x1 = r.y;
    const float h = r.z - r.x;
    const float w = r.w - r.y;

    const int lvl = roi_level(h, w, img_area);
    const float* feat;
    int H;
    switch (lvl) {
        case 2:  feat = p2; H = 256; break;
        case 3:  feat = p3; H = 128; break;
        case 4:  feat = p4; H = 64;  break;
        default: feat = p5; H = 32;  break;
    }
    const float Hm1 = (float)(H - 1);
    const float Hm2 = (float)(H - 2);
    feat += (size_t)b * (size_t)H * (size_t)H * C;

    const float ysf = (y1 + gy * h) * Hm1;
    const float y0f = fminf(fmaxf(floorf(ysf), 0.0f), Hm2);
    const int   y0  = (int)y0f;
    const float ty  = fminf(fmaxf(ysf - y0f, 0.0f), 1.0f);
    c.wty2 = f32x2_pack(1.0f - ty);
    c.ty2  = f32x2_pack(ty);

    c.row0 = reinterpret_cast<const ulonglong2*>(feat) + (size_t)y0 * H * 64 + lane;
    c.row1 = c.row0 + (size_t)H * 64;

#pragma unroll
    for (int px = 0; px < POOL; ++px) {
        const float gx  = (float)px * (1.0f / (POOL - 1));
        const float xsf = (x1 + gx * w) * Hm1;
        const float x0f = fminf(fmaxf(floorf(xsf), 0.0f), Hm2);
        c.xo[px]  = (int)x0f * 64;
        c.txa[px] = fminf(fmaxf(xsf - x0f, 0.0f), 1.0f);
    }

    c.outb = reinterpret_cast<float4*>(out + (size_t)bn * (POOL * POOL * C))
             + (size_t)py * POOL * 64 + lane;
}

// v layout: [0]=s00a [1]=s00b [2]=s01a [3]=s01b [4]=s10a [5]=s10b [6]=s11a [7]=s11b
__device__ __forceinline__ void roi_px(const Ctx& c, ulonglong2 v[8], int& cx, int px)
{
    const int x = c.xo[px];
    if (x == cx + 64) {
        v[0] = v[2]; v[1] = v[3]; v[4] = v[6]; v[5] = v[7];
        const ulonglong2* q0 = c.row0 + (x + 64);
        const ulonglong2* q1 = c.row1 + (x + 64);
        v[2] = q0[0]; v[3] = q0[32];
        v[6] = q1[0]; v[7] = q1[32];
    } else if (x != cx) {
        const ulonglong2* q0 = c.row0 + x;
        const ulonglong2* q1 = c.row1 + x;
        v[0] = q0[0];  v[1] = q0[32];
        v[2] = q0[64]; v[3] = q0[96];
        v[4] = q1[0];  v[5] = q1[32];
        v[6] = q1[64]; v[7] = q1[96];
    }
    cx = x;

    const float tx = c.txa[px];
    const u64 wtx2 = f32x2_pack(1.0f - tx);
    const u64 tx2  = f32x2_pack(tx);

    ulonglong2 ra, rb;
    ra.x = bilerp2(v[0].x, v[2].x, v[4].x, v[6].x, wtx2, tx2, c.wty2, c.ty2);
    ra.y = bilerp2(v[0].y, v[2].y, v[4].y, v[6].y, wtx2, tx2, c.wty2, c.ty2);
    rb.x = bilerp2(v[1].x, v[3].x, v[5].x, v[7].x, wtx2, tx2, c.wty2, c.ty2);
    rb.y = bilerp2(v[1].y, v[3].y, v[5].y, v[7].y, wtx2, tx2, c.wty2, c.ty2);

    __stcs(c.outb + px * 64,      *reinterpret_cast<float4*>(&ra));
    __stcs(c.outb + px * 64 + 32, *reinterpret_cast<float4*>(&rb));
}

// One block = 2 bucket-adjacent ROIs, px-interleaved for L1 cross-ROI capture.
// Block (32,7): warp = pooled row, lane = channel quad (covers lane, lane+32).
__global__ __launch_bounds__(224, 2)
void roi_align_kernel(const float* __restrict__ rois,
                      const int*   __restrict__ image_shape,
                      const float* __restrict__ p2,
                      const float* __restrict__ p3,
                      const float* __restrict__ p4,
                      const float* __restrict__ p5,
                      float* __restrict__ out,
                      int N, int BN)
{
    const int lane = threadIdx.x;
    const int py   = threadIdx.y;
    const float gy = (float)py * (1.0f / (POOL - 1));
    const float img_area = (float)image_shape[0] * (float)image_shape[1];

    const int slotA = blockIdx.x * 2;
    const int slotB = slotA + 1;
    const bool hasB = (slotB < BN);

    Ctx A, B;
    setup_ctx(A, g_order[slotA], N, rois, img_area, p2, p3, p4, p5, out, lane, gy, py);
    if (hasB)
        setup_ctx(B, g_order[slotB], N, rois, img_area, p2, p3, p4, p5, out, lane, gy, py);

    ulonglong2 va[8], vb[8];
    int cxA = -128, cxB = -128;

#pragma unroll
    for (int px = 0; px < POOL; ++px) {
        roi_px(A, va, cxA, px);
        if (hasB) roi_px(B, vb, cxB, px);
    }
}

extern "C" void kernel_launch(void* const* d_in, const int* in_sizes, int n_in,
                              void* d_out, int out_size)
{
    const float* rois        = (const float*)d_in[0];
    const int*   image_shape = (const int*)  d_in[1];
    const float* p2          = (const float*)d_in[2];
    const float* p3          = (const float*)d_in[3];
    const float* p4          = (const float*)d_in[4];
    const float* p5          = (const float*)d_in[5];
    float*       out         = (float*)d_out;

    const int B  = in_sizes[2] / (256 * 256 * 256);
    const int N  = in_sizes[0] / (4 * B);
    const int BN = B * N;

    bin_kernel<<<1, NB>>>(rois, image_shape, BN, N);

    dim3 block(32, 7);
    dim3 grid((BN + 1) / 2);
    roi_align_kernel<<<grid, block>>>(rois, image_shape, p2, p3, p4, p5, out, N, BN);
}

// round 9
// speedup vs baseline: 1.2252x; 1.2080x over previous
#include <cuda_runtime.h>
#include <math.h>

#define POOL 7
#define C 256

typedef unsigned long long u64;

__device__ __forceinline__ u64 f32x2_mul(u64 a, u64 b) {
    u64 d; asm("mul.rn.f32x2 %0, %1, %2;" : "=l"(d) : "l"(a), "l"(b)); return d;
}
__device__ __forceinline__ u64 f32x2_fma(u64 a, u64 b, u64 c) {
    u64 d; asm("fma.rn.f32x2 %0, %1, %2, %3;" : "=l"(d) : "l"(a), "l"(b), "l"(c)); return d;
}
__device__ __forceinline__ u64 f32x2_pack(float v) {
    u64 d; asm("mov.b64 %0, {%1, %1};" : "=l"(d) : "f"(v)); return d;
}
__device__ __forceinline__ u64 bilerp2(u64 v00, u64 v01, u64 v10, u64 v11,
                                       u64 wtx2, u64 tx2, u64 wty2, u64 ty2) {
    u64 top = f32x2_fma(v01, tx2, f32x2_mul(v00, wtx2));
    u64 bot = f32x2_fma(v11, tx2, f32x2_mul(v10, wtx2));
    return f32x2_fma(bot, ty2, f32x2_mul(top, wty2));
}

// Two blocks per ROI (channel halves). Block (32,7): warp = pooled row,
// lane = one channel quad within the half. Column-carry walk over the 7
// pooled columns (x0 non-decreasing, block-uniform -> no divergence).
// Halved carry state vs the full-pixel version -> ~50 regs -> 5 CTAs/SM.
__global__ __launch_bounds__(224, 5)
void roi_align_kernel(const float* __restrict__ rois,
                      const int*   __restrict__ image_shape,
                      const float* __restrict__ p2,
                      const float* __restrict__ p3,
                      const float* __restrict__ p4,
                      const float* __restrict__ p5,
                      float* __restrict__ out,
                      int N)
{
    const int blk  = blockIdx.x;
    const int bn   = blk >> 1;
    const int half = blk & 1;
    const int b    = bn / N;

    const float4 r = reinterpret_cast<const float4*>(rois)[bn];
    const float y1 = r.x, x1 = r.y, y2 = r.z, x2 = r.w;
    const float h = y2 - y1;
    const float w = x2 - x1;

    const float img_area = (float)image_shape[0] * (float)image_shape[1];
    const float scale = sqrtf(fmaxf(h * w, 1e-12f)) * (sqrtf(img_area) / 224.0f);
    int lvl = 4 + (int)rintf(log2f(scale));   // round-half-even == jnp.round
    lvl = min(max(lvl, 2), 5);

    const float* feat;
    int H;
    switch (lvl) {
        case 2:  feat = p2; H = 256; break;
        case 3:  feat = p3; H = 128; break;
        case 4:  feat = p4; H = 64;  break;
        default: feat = p5; H = 32;  break;
    }
    const float Hm1 = (float)(H - 1);
    const float Hm2 = (float)(H - 2);
    feat += (size_t)b * (size_t)H * (size_t)H * C;

    const int lane = threadIdx.x;           // quad within half: 0..31
    const int py   = threadIdx.y;           // pooled row (warp-uniform)
    const int q    = half * 32 + lane;      // absolute quad 0..63

    // ---- y coordinate (warp-uniform) ----
    const float gy  = (float)py * (1.0f / (POOL - 1));
    const float ysf = (y1 + gy * h) * Hm1;
    const float y0f = fminf(fmaxf(floorf(ysf), 0.0f), Hm2);
    const int   y0  = (int)y0f;
    const float ty  = fminf(fmaxf(ysf - y0f, 0.0f), 1.0f);
    const u64 wty2 = f32x2_pack(1.0f - ty);
    const u64 ty2  = f32x2_pack(ty);

    const ulonglong2* row0 = reinterpret_cast<const ulonglong2*>(feat) +
                             (size_t)y0 * H * 64 + q;
    const ulonglong2* row1 = row0 + (size_t)H * 64;

    // ---- precompute 7 x offsets (quad units, non-decreasing) + fractions ----
    int   xo[POOL];
    float txa[POOL];
#pragma unroll
    for (int px = 0; px < POOL; ++px) {
        const float gx  = (float)px * (1.0f / (POOL - 1));
        const float xsf = (x1 + gx * w) * Hm1;
        const float x0f = fminf(fmaxf(floorf(xsf), 0.0f), Hm2);
        xo[px]  = (int)x0f * 64;
        txa[px] = fminf(fmaxf(xsf - x0f, 0.0f), 1.0f);
    }

    float4* out_base = reinterpret_cast<float4*>(out + (size_t)bn * (POOL * POOL * C))
                       + (size_t)py * POOL * 64 + q;

    // Column-carry state: columns (cx, cx+1) for rows y0, y0+1 (one quad each).
    ulonglong2 s00, s01, s10, s11;
    int cx = -128;   // sentinel: forces full load at px=0

#pragma unroll
    for (int px = 0; px < POOL; ++px) {
        const int x = xo[px];
        if (x == cx + 64) {
            // shift right column -> left, load one new column (2 LDG.128)
            s00 = s01;
            s10 = s11;
            s01 = row0[x + 64];
            s11 = row1[x + 64];
        } else if (x != cx) {
            // fresh pair of columns (4 LDG.128)
            s00 = row0[x];
            s01 = row0[x + 64];
            s10 = row1[x];
            s11 = row1[x + 64];
        }
        cx = x;

        const float tx = txa[px];
        const u64 wtx2 = f32x2_pack(1.0f - tx);
        const u64 tx2  = f32x2_pack(tx);

        ulonglong2 res;
        res.x = bilerp2(s00.x, s01.x, s10.x, s11.x, wtx2, tx2, wty2, ty2);
        res.y = bilerp2(s00.y, s01.y, s10.y, s11.y, wtx2, tx2, wty2, ty2);

        __stcs(out_base + px * 64, *reinterpret_cast<float4*>(&res));
    }
}

extern "C" void kernel_launch(void* const* d_in, const int* in_sizes, int n_in,
                              void* d_out, int out_size)
{
    const float* rois        = (const float*)d_in[0];
    const int*   image_shape = (const int*)  d_in[1];
    const float* p2          = (const float*)d_in[2];
    const float* p3          = (const float*)d_in[3];
    const float* p4          = (const float*)d_in[4];
    const float* p5          = (const float*)d_in[5];
    float*       out         = (float*)d_out;

    const int B = in_sizes[2] / (256 * 256 * 256);
    const int N = in_sizes[0] / (4 * B);

    dim3 block(32, 7);
    dim3 grid(B * N * 2);
    roi_align_kernel<<<grid, block>>>(rois, image_shape, p2, p3, p4, p5, out, N);
}

// round 10
// speedup vs baseline: 1.3668x; 1.1156x over previous
#include <cuda_runtime.h>
#include <math.h>

#define POOL 7
#define C 256

typedef unsigned long long u64;

__device__ __forceinline__ u64 f32x2_mul(u64 a, u64 b) {
    u64 d; asm("mul.rn.f32x2 %0, %1, %2;" : "=l"(d) : "l"(a), "l"(b)); return d;
}
__device__ __forceinline__ u64 f32x2_fma(u64 a, u64 b, u64 c) {
    u64 d; asm("fma.rn.f32x2 %0, %1, %2, %3;" : "=l"(d) : "l"(a), "l"(b), "l"(c)); return d;
}
__device__ __forceinline__ u64 f32x2_pack(float v) {
    u64 d; asm("mov.b64 %0, {%1, %1};" : "=l"(d) : "f"(v)); return d;
}
__device__ __forceinline__ u64 bilerp2(u64 v00, u64 v01, u64 v10, u64 v11,
                                       u64 wtx2, u64 tx2, u64 wty2, u64 ty2) {
    u64 top = f32x2_fma(v01, tx2, f32x2_mul(v00, wtx2));
    u64 bot = f32x2_fma(v11, tx2, f32x2_mul(v10, wtx2));
    return f32x2_fma(bot, ty2, f32x2_mul(top, wty2));
}

// One block per ROI (R6 structure). Block (32,7): warp = pooled row,
// lane = channel quad (covers quads lane and lane+32). Column-carry walk
// over the 7 pooled columns (x0 non-decreasing, block-uniform).
// Register diet: only raw float x-coords are kept (xsa[7]); x0/tx are
// re-derived per px so the kernel fits 5 CTAs/SM.
__global__ __launch_bounds__(224, 5)
void roi_align_kernel(const float* __restrict__ rois,
                      const int*   __restrict__ image_shape,
                      const float* __restrict__ p2,
                      const float* __restrict__ p3,
                      const float* __restrict__ p4,
                      const float* __restrict__ p5,
                      float* __restrict__ out,
                      int N)
{
    const int bn = blockIdx.x;
    const int b  = bn / N;

    const float4 r = reinterpret_cast<const float4*>(rois)[bn];
    const float y1 = r.x, x1 = r.y, y2 = r.z, x2 = r.w;
    const float h = y2 - y1;
    const float w = x2 - x1;

    const float img_area = (float)image_shape[0] * (float)image_shape[1];
    const float scale = sqrtf(fmaxf(h * w, 1e-12f)) * (sqrtf(img_area) / 224.0f);
    int lvl = 4 + (int)rintf(log2f(scale));   // round-half-even == jnp.round
    lvl = min(max(lvl, 2), 5);

    const float* feat;
    int H;
    switch (lvl) {
        case 2:  feat = p2; H = 256; break;
        case 3:  feat = p3; H = 128; break;
        case 4:  feat = p4; H = 64;  break;
        default: feat = p5; H = 32;  break;
    }
    const float Hm1 = (float)(H - 1);
    const float Hm2 = (float)(H - 2);
    feat += (size_t)b * (size_t)H * (size_t)H * C;

    const int lane = threadIdx.x;   // channel quad (and +32)
    const int py   = threadIdx.y;   // pooled row (warp-uniform)

    // ---- y coordinate (warp-uniform) ----
    const float gy  = (float)py * (1.0f / (POOL - 1));
    const float ysf = (y1 + gy * h) * Hm1;
    const float y0f = fminf(fmaxf(floorf(ysf), 0.0f), Hm2);
    const int   y0  = (int)y0f;
    const float ty  = fminf(fmaxf(ysf - y0f, 0.0f), 1.0f);
    const u64 wty2 = f32x2_pack(1.0f - ty);
    const u64 ty2  = f32x2_pack(ty);

    const ulonglong2* row0 = reinterpret_cast<const ulonglong2*>(feat) +
                             (size_t)y0 * H * 64 + lane;
    const ulonglong2* row1 = row0 + (size_t)H * 64;

    // ---- precompute only the 7 raw x coords (floats) ----
    float xsa[POOL];
#pragma unroll
    for (int px = 0; px < POOL; ++px) {
        const float gx = (float)px * (1.0f / (POOL - 1));
        xsa[px] = (x1 + gx * w) * Hm1;
    }

    float4* out_base = reinterpret_cast<float4*>(out + (size_t)bn * (POOL * POOL * C))
                       + (size_t)py * POOL * 64 + lane;

    // Column-carry state: columns (cx, cx+1) for rows y0, y0+1; a = quad lane,
    // b = quad lane+32.
    ulonglong2 s00a, s00b, s01a, s01b, s10a, s10b, s11a, s11b;
    int cx = -128;   // sentinel: forces full load at px=0

#pragma unroll
    for (int px = 0; px < POOL; ++px) {
        // re-derive x0 / tx from the stored float coordinate (saves regs)
        const float xsf = xsa[px];
        const float x0f = fminf(fmaxf(floorf(xsf), 0.0f), Hm2);
        const int   x   = (int)x0f * 64;
        const float tx  = fminf(fmaxf(xsf - x0f, 0.0f), 1.0f);

        if (x == cx + 64) {
            // shift right column -> left, load one new column (4 LDG.128)
            s00a = s01a; s00b = s01b;
            s10a = s11a; s10b = s11b;
            const ulonglong2* q0 = row0 + (x + 64);
            const ulonglong2* q1 = row1 + (x + 64);
            s01a = q0[0]; s01b = q0[32];
            s11a = q1[0]; s11b = q1[32];
        } else if (x != cx) {
            // fresh pair of columns (8 LDG.128)
            const ulonglong2* q0 = row0 + x;
            const ulonglong2* q1 = row1 + x;
            s00a = q0[0];  s00b = q0[32];
            s01a = q0[64]; s01b = q0[96];
            s10a = q1[0];  s10b = q1[32];
            s11a = q1[64]; s11b = q1[96];
        }
        cx = x;

        const u64 wtx2 = f32x2_pack(1.0f - tx);
        const u64 tx2  = f32x2_pack(tx);

        ulonglong2 ra, rb;
        ra.x = bilerp2(s00a.x, s01a.x, s10a.x, s11a.x, wtx2, tx2, wty2, ty2);
        ra.y = bilerp2(s00a.y, s01a.y, s10a.y, s11a.y, wtx2, tx2, wty2, ty2);
        rb.x = bilerp2(s00b.x, s01b.x, s10b.x, s11b.x, wtx2, tx2, wty2, ty2);
        rb.y = bilerp2(s00b.y, s01b.y, s10b.y, s11b.y, wtx2, tx2, wty2, ty2);

        __stcs(out_base + px * 64,      *reinterpret_cast<float4*>(&ra));
        __stcs(out_base + px * 64 + 32, *reinterpret_cast<float4*>(&rb));
    }
}

extern "C" void kernel_launch(void* const* d_in, const int* in_sizes, int n_in,
                              void* d_out, int out_size)
{
    const float* rois        = (const float*)d_in[0];
    const int*   image_shape = (const int*)  d_in[1];
    const float* p2          = (const float*)d_in[2];
    const float* p3          = (const float*)d_in[3];
    const float* p4          = (const float*)d_in[4];
    const float* p5          = (const float*)d_in[5];
    float*       out         = (float*)d_out;

    const int B = in_sizes[2] / (256 * 256 * 256);
    const int N = in_sizes[0] / (4 * B);

    dim3 block(32, 7);
    dim3 grid(B * N);
    roi_align_kernel<<<grid, block>>>(rois, image_shape, p2, p3, p4, p5, out, N);
}